// round 16
// baseline (speedup 1.0000x reference)
#include <cuda_runtime.h>

typedef unsigned long long u64;
typedef unsigned int u32;

#define TPB   128
#define EPW   2                     // elements per warp (16 lanes each)
#define EPB   8                     // elements per block
#define TROW  32                    // words per t-row
#define IMG   904                   // 28*32 + 8 skew; adjacent elems 8 banks apart
#define XW    (EPB * IMG)           // 7232 words
#define SMEMW (XW + 64)             // pad covers t=28 pipeline prefetch; ~29.2 KB

// byte-LUT in gmem (L1D-cached): [p4][byte][j], j stride 10; b2 folded into p4=0
__device__ float g_lut[4 * 256 * 10];

// ---- packed fp32x2 helpers (sm_103a dual-fp32: 2x FFMA throughput) ----
__device__ __forceinline__ u64 pk(float lo, float hi) {
    u64 r; asm("mov.b64 %0, {%1, %2};" : "=l"(r) : "f"(lo), "f"(hi)); return r;
}
__device__ __forceinline__ void upk(float& lo, float& hi, u64 v) {
    asm("mov.b64 {%0, %1}, %2;" : "=f"(lo), "=f"(hi) : "l"(v));
}
__device__ __forceinline__ u64 fma2(u64 a, u64 b, u64 c) {
    u64 d; asm("fma.rn.f32x2 %0, %1, %2, %3;" : "=l"(d) : "l"(a), "l"(b), "l"(c)); return d;
}
__device__ __forceinline__ u64 add2(u64 a, u64 b) {
    u64 d; asm("add.rn.f32x2 %0, %1, %2;" : "=l"(d) : "l"(a), "l"(b)); return d;
}

// layer-1 for timestep tt, units u and u+16 (i-pair packed accumulators, R15 order)
#define COMPUTE_H(tt, HL, HH)                                                   \
    do {                                                                        \
        const ulonglong2* xr_ =                                                 \
            reinterpret_cast<const ulonglong2*>(xbase + (tt) * TROW);           \
        u64 aL = hbL, aH = hbH;                                                 \
        _Pragma("unroll")                                                       \
        for (int k = 0; k < 7; ++k) {                                           \
            ulonglong2 xp = xr_[k];            /* (x4k,x4k+1),(x4k+2,x4k+3) */  \
            aL = fma2(xp.x, wL[2 * k], aL);                                     \
            aH = fma2(xp.x, wH[2 * k], aH);                                     \
            aL = fma2(xp.y, wL[2 * k + 1], aL);                                 \
            aH = fma2(xp.y, wH[2 * k + 1], aH);                                 \
        }                                                                       \
        { float lo_, hi_;                                                       \
          upk(lo_, hi_, aL); (HL) = lo_ + hi_;                                  \
          upk(lo_, hi_, aH); (HH) = lo_ + hi_; }                                \
    } while (0)

// ======== prologue kernel: build byte-LUT (R13's exact fp order, b2 folded) ======
__global__ void build_lut(const float* __restrict__ W2, const float* __restrict__ b2)
{
    int idx = blockIdx.x * blockDim.x + threadIdx.x;
    if (idx < 4 * 256 * 10) {
        int j  = idx % 10;
        int vv = (idx / 10) & 255;
        int p4 = idx / 2560;
        float slo = 0.0f, shi = 0.0f;
#pragma unroll
        for (int bb = 0; bb < 4; ++bb)
            if ((vv >> bb) & 1) slo += W2[j * 32 + 8 * p4 + bb];
#pragma unroll
        for (int bb = 0; bb < 4; ++bb)
            if ((vv >> (4 + bb)) & 1) shi += W2[j * 32 + 8 * p4 + 4 + bb];
        float s = slo + shi;
        if (p4 == 0) s = b2[j] + s;     // b2 + entry0: identical to add2(b2p, l0)
        g_lut[idx] = s;
    }
}

extern __shared__ __align__(16) float smem_f[];

__global__ void __launch_bounds__(TPB, 4) snn_kernel(
    const float* __restrict__ x,  const float* __restrict__ W1,
    const float* __restrict__ b1, const float* __restrict__ W2,
    const float* __restrict__ b2, float* __restrict__ out, int B)
{
    float* smx = smem_f;            // staged x, t-major rows

    const int tid = threadIdx.x;
    const int lid = tid & 31;
    const int wid = tid >> 5;
    const int half = lid >> 4;      // elem within warp (0..1)
    const int u    = lid & 15;      // owns units u and u+16
    const int eLocal = wid * EPW + half;
    const int gbase  = blockIdx.x * EPB;

    // ======== stage x: [e][t][i] rows (float4 LDG, scalar STS) ========
    for (int task = tid; task < EPB * 28; task += TPB) {
        int e = task / 28, i = task - e * 28;
        if (gbase + e < B) {
            const float4* src = reinterpret_cast<const float4*>(
                x + (size_t)(gbase + e) * 784 + i * 28);
            float* dst = smx + e * IMG + i;
#pragma unroll
            for (int c = 0; c < 7; ++c) {
                float4 v4 = __ldg(src + c);
                dst[(4 * c + 0) * TROW] = v4.x;
                dst[(4 * c + 1) * TROW] = v4.y;
                dst[(4 * c + 2) * TROW] = v4.z;
                dst[(4 * c + 3) * TROW] = v4.w;
            }
        }
    }

    // ======== per-lane weights, i-pair packed: w[m] = (W1[u][2m], W1[u][2m+1]) ====
    u64 wL[14], wH[14];
    {
        const ulonglong2* qL = reinterpret_cast<const ulonglong2*>(W1 + u * 28);
        const ulonglong2* qH = reinterpret_cast<const ulonglong2*>(W1 + (u + 16) * 28);
#pragma unroll
        for (int c = 0; c < 7; ++c) {
            ulonglong2 a = __ldg(qL + c); wL[2 * c] = a.x; wL[2 * c + 1] = a.y;
            ulonglong2 b = __ldg(qH + c); wH[2 * c] = b.x; wH[2 * c + 1] = b.y;
        }
    }
    const u64 hbL = pk(__ldg(&b1[u]),      0.0f);
    const u64 hbH = pk(__ldg(&b1[u + 16]), 0.0f);

    // layer-2 lane roles: lanes 0..9 -> (elem me, output-pair jj); others mirror
    const int jj = lid % 5;
    const int me = (lid / 5) & 1;
    const float* lj = g_lut + 2 * jj;
    const u32 psel = me ? 0x7632u : 0x5410u;   // half-word select of elem 'me'

    __syncthreads();

    // ================= software-pipelined main recurrence (rolled) ================
    const float* xbase = smx + eLocal * IMG;

    float mL = 0.0f, mH = 0.0f;      // membranes for units u, u+16
    u64 v2p = 0ull;
    int ac0 = 0, ac1 = 0;            // integer spike counters (exact)
    float hLc, hHc;
    COMPUTE_H(0, hLc, hHc);          // prologue: h for t=0

#pragma unroll 2
    for (int t = 0; t < 28; ++t) {
        // ---- IF layer 1 + 2 spike ballots ----
        mL += hLc; mH += hHc;
        bool sL = (mL >= 1.0f);      // unit u
        bool sH = (mH >= 1.0f);      // unit u+16
        u32 B0 = __ballot_sync(0xffffffffu, sL);   // bit l = unit (l&15), elem l>>4
        u32 B1 = __ballot_sync(0xffffffffu, sH);   // bit l = unit (l&15)+16
        mL = sL ? 0.0f : mL;
        mH = sH ? 0.0f : mH;

        // ---- 32-bit spike mask of elem 'me': single PRMT ----
        u32 M = __byte_perm(B0, B1, psel);

        // ---- issue 4 byte-LUT LDGs now (L1D-resident, b2 folded in p4=0) ----
        u64 l0 = __ldg(reinterpret_cast<const u64*>(lj + (M & 255u) * 10));
        u64 l1 = __ldg(reinterpret_cast<const u64*>(lj + ((M >> 8)  & 255u) * 10 + 2560));
        u64 l2 = __ldg(reinterpret_cast<const u64*>(lj + ((M >> 16) & 255u) * 10 + 5120));
        u64 l3 = __ldg(reinterpret_cast<const u64*>(lj + (M >> 24) * 10 + 7680));

        // ---- overlap: h for t+1 (t=27 prefetch discarded; in-bounds smem) ----
        float hLn, hHn;
        COMPUTE_H(t + 1, hLn, hHn);

        // ---- layer 2: serial ascending-p4 (exact R13 order) ----
        u64 h2 = l0;
        h2 = add2(h2, l1); h2 = add2(h2, l2); h2 = add2(h2, l3);

        // ---- IF layer 2 + integer rate accumulation ----
        v2p = add2(v2p, h2);
        float g0, g1; upk(g0, g1, v2p);
        bool t0 = (g0 >= 1.0f), t1 = (g1 >= 1.0f);
        ac0 += t0; ac1 += t1;
        v2p = pk(t0 ? 0.0f : g0, t1 ? 0.0f : g1);

        hLc = hLn; hHc = hHn;
    }

    // ---- output: lanes 0..9 write their (elem, j-pair) firing rates ----
    int ge = gbase + wid * EPW + me;
    if (lid < 10 && ge < B) {
        *reinterpret_cast<float2*>(out + (size_t)ge * 10 + 2 * jj) =
            make_float2((float)ac0 * (1.0f / 28.0f), (float)ac1 * (1.0f / 28.0f));
    }
}

extern "C" void kernel_launch(void* const* d_in, const int* in_sizes, int n_in,
                              void* d_out, int out_size) {
    const float* x  = (const float*)d_in[0];
    const float* W1 = (const float*)d_in[1];
    const float* b1 = (const float*)d_in[2];
    const float* W2 = (const float*)d_in[3];
    const float* b2 = (const float*)d_in[4];
    float* out = (float*)d_out;

    int B = in_sizes[0] / 784;
    int smem = SMEMW * (int)sizeof(float);   // ~29.2 KB -> smem allows 4+ blocks/SM

    cudaFuncSetAttribute(snn_kernel, cudaFuncAttributeMaxDynamicSharedMemorySize, smem);

    build_lut<<<40, 256>>>(W2, b2);           // 10240 entries, one per thread

    int grid = (B + EPB - 1) / EPB;
    snn_kernel<<<grid, TPB, smem>>>(x, W1, b1, W2, b2, out, B);
}

// round 17
// speedup vs baseline: 1.1548x; 1.1548x over previous
#include <cuda_runtime.h>

typedef unsigned long long u64;
typedef unsigned int u32;

#define TPB   128
#define EPW   4                     // elements per warp
#define EPB   16                    // elements per block
#define TROW  32                    // words per t-row
#define IMG   904                   // 28*32 + 8 skew; 904%32=8 -> elem quads disjoint
#define XW    (EPB * IMG)           // 14464 words
#define SMEMW (XW + 64)             // pad covers pipeline prefetch slack

// byte-LUT in gmem (L1D-cached): [p4][byte][j], j stride 10; b2 folded into p4=0
__device__ float g_lut[4 * 256 * 10];

// ---- packed fp32x2 helpers (sm_103a dual-fp32: 2x FFMA throughput) ----
__device__ __forceinline__ u64 pk(float lo, float hi) {
    u64 r; asm("mov.b64 %0, {%1, %2};" : "=l"(r) : "f"(lo), "f"(hi)); return r;
}
__device__ __forceinline__ void upk(float& lo, float& hi, u64 v) {
    asm("mov.b64 {%0, %1}, %2;" : "=f"(lo), "=f"(hi) : "l"(v));
}
__device__ __forceinline__ u64 fma2(u64 a, u64 b, u64 c) {
    u64 d; asm("fma.rn.f32x2 %0, %1, %2, %3;" : "=l"(d) : "l"(a), "l"(b), "l"(c)); return d;
}
__device__ __forceinline__ u64 add2(u64 a, u64 b) {
    u64 d; asm("add.rn.f32x2 %0, %1, %2;" : "=l"(d) : "l"(a), "l"(b)); return d;
}

// layer-1 chains for timestep tt, split i 0..15 / 16..27 -> 4 independent chains
// (merge = 1 add2 per h; reassociation proven safe in R15/R16: rel_err 0.0)
#define COMPUTE_H(tt, H0, H1)                                                   \
    do {                                                                        \
        const float4* xr_ = reinterpret_cast<const float4*>(xbase + (tt) * TROW); \
        u64 c00 = hb0, c10 = hb1, c01 = 0ull, c11 = 0ull;                       \
        _Pragma("unroll")                                                       \
        for (int k = 0; k < 4; ++k) {                                           \
            float4 xv = xr_[k];                                                 \
            u64 d0 = pk(xv.x, xv.x);                                            \
            c00 = fma2(d0, wA[4 * k + 0], c00);                                 \
            c10 = fma2(d0, wB[4 * k + 0], c10);                                 \
            u64 d1 = pk(xv.y, xv.y);                                            \
            c00 = fma2(d1, wA[4 * k + 1], c00);                                 \
            c10 = fma2(d1, wB[4 * k + 1], c10);                                 \
            u64 d2 = pk(xv.z, xv.z);                                            \
            c00 = fma2(d2, wA[4 * k + 2], c00);                                 \
            c10 = fma2(d2, wB[4 * k + 2], c10);                                 \
            u64 d3 = pk(xv.w, xv.w);                                            \
            c00 = fma2(d3, wA[4 * k + 3], c00);                                 \
            c10 = fma2(d3, wB[4 * k + 3], c10);                                 \
        }                                                                       \
        _Pragma("unroll")                                                       \
        for (int k = 4; k < 7; ++k) {                                           \
            float4 xv = xr_[k];                                                 \
            u64 d0 = pk(xv.x, xv.x);                                            \
            c01 = fma2(d0, wA[4 * k + 0], c01);                                 \
            c11 = fma2(d0, wB[4 * k + 0], c11);                                 \
            u64 d1 = pk(xv.y, xv.y);                                            \
            c01 = fma2(d1, wA[4 * k + 1], c01);                                 \
            c11 = fma2(d1, wB[4 * k + 1], c11);                                 \
            u64 d2 = pk(xv.z, xv.z);                                            \
            c01 = fma2(d2, wA[4 * k + 2], c01);                                 \
            c11 = fma2(d2, wB[4 * k + 2], c11);                                 \
            u64 d3 = pk(xv.w, xv.w);                                            \
            c01 = fma2(d3, wA[4 * k + 3], c01);                                 \
            c11 = fma2(d3, wB[4 * k + 3], c11);                                 \
        }                                                                       \
        (H0) = add2(c00, c01);                                                  \
        (H1) = add2(c10, c11);                                                  \
    } while (0)

// ======== prologue kernel: build byte-LUT (R13's exact fp order, b2 folded) ======
__global__ void build_lut(const float* __restrict__ W2, const float* __restrict__ b2)
{
    int idx = blockIdx.x * blockDim.x + threadIdx.x;
    if (idx < 4 * 256 * 10) {
        int j  = idx % 10;
        int vv = (idx / 10) & 255;
        int p4 = idx / 2560;
        float slo = 0.0f, shi = 0.0f;
#pragma unroll
        for (int bb = 0; bb < 4; ++bb)
            if ((vv >> bb) & 1) slo += W2[j * 32 + 8 * p4 + bb];
#pragma unroll
        for (int bb = 0; bb < 4; ++bb)
            if ((vv >> (4 + bb)) & 1) shi += W2[j * 32 + 8 * p4 + 4 + bb];
        float s = slo + shi;
        if (p4 == 0) s = b2[j] + s;     // identical to add2(b2p, l0) bias-first
        g_lut[idx] = s;
    }
}

extern __shared__ __align__(16) float smem_f[];

__global__ void __launch_bounds__(TPB, 3) snn_kernel(
    const float* __restrict__ x,  const float* __restrict__ W1,
    const float* __restrict__ b1, const float* __restrict__ W2,
    const float* __restrict__ b2, float* __restrict__ out, int B)
{
    float* smx = smem_f;            // staged x, t-major rows

    const int tid = threadIdx.x;
    const int lid = tid & 31;
    const int wid = tid >> 5;
    const int q   = lid >> 3;       // elem within warp (0..3)
    const int r   = lid & 7;        // unit-slice (0..7)
    const int eLocal = wid * EPW + q;
    const int gbase  = blockIdx.x * EPB;

    // ======== stage x: [e][t][i] rows (float4 LDG, scalar STS) ========
    for (int task = tid; task < EPB * 28; task += TPB) {
        int e = task / 28, i = task - e * 28;
        if (gbase + e < B) {
            const float4* src = reinterpret_cast<const float4*>(
                x + (size_t)(gbase + e) * 784 + i * 28);
            float* dst = smx + e * IMG + i;
#pragma unroll
            for (int c = 0; c < 7; ++c) {
                float4 v4 = __ldg(src + c);
                dst[(4 * c + 0) * TROW] = v4.x;
                dst[(4 * c + 1) * TROW] = v4.y;
                dst[(4 * c + 2) * TROW] = v4.z;
                dst[(4 * c + 3) * TROW] = v4.w;
            }
        }
    }

    // ======== per-lane register weights: unit-pairs (r, r+16) and (r+8, r+24) ======
    u64 wA[28], wB[28];
    {
        const float4* p0 = reinterpret_cast<const float4*>(W1 + r * 28);
        const float4* p1 = reinterpret_cast<const float4*>(W1 + (r + 16) * 28);
        const float4* p2 = reinterpret_cast<const float4*>(W1 + (r + 8) * 28);
        const float4* p3 = reinterpret_cast<const float4*>(W1 + (r + 24) * 28);
#pragma unroll
        for (int c = 0; c < 7; ++c) {
            float4 a = __ldg(p0 + c), b = __ldg(p1 + c);
            float4 e = __ldg(p2 + c), f = __ldg(p3 + c);
            wA[4 * c + 0] = pk(a.x, b.x); wA[4 * c + 1] = pk(a.y, b.y);
            wA[4 * c + 2] = pk(a.z, b.z); wA[4 * c + 3] = pk(a.w, b.w);
            wB[4 * c + 0] = pk(e.x, f.x); wB[4 * c + 1] = pk(e.y, f.y);
            wB[4 * c + 2] = pk(e.z, f.z); wB[4 * c + 3] = pk(e.w, f.w);
        }
    }
    const u64 hb0 = pk(__ldg(&b1[r]),     __ldg(&b1[r + 16]));
    const u64 hb1 = pk(__ldg(&b1[r + 8]), __ldg(&b1[r + 24]));

    // layer-2 lane roles: lanes 0..19 -> (elem me, output-pair jj); 20..31 mirror
    const int jj = lid % 5;
    const int me = (lid / 5) & 3;
    const float* lj = g_lut + 2 * jj;
    const u32 sel = (u32)me | (((u32)me + 4) << 4);   // byte_perm: byte 'me' of a,b

    __syncthreads();

    // ================= software-pipelined main recurrence (rolled) ================
    const float* xbase = smx + eLocal * IMG;

    u64 v1a = 0ull, v1b = 0ull, v2p = 0ull;
    int ac0 = 0, ac1 = 0;            // integer spike counters (exact)
    u64 hc0, hc1;
    COMPUTE_H(0, hc0, hc1);          // prologue: h for t=0

#pragma unroll 2
    for (int t = 0; t < 28; ++t) {
        // ---- IF layer 1 on current h + spike ballots ----
        v1a = add2(v1a, hc0);
        v1b = add2(v1b, hc1);
        float fa0, fa1, fb0, fb1;
        upk(fa0, fa1, v1a);
        upk(fb0, fb1, v1b);
        bool sr0  = (fa0 >= 1.0f);      // unit r
        bool sr16 = (fa1 >= 1.0f);      // unit r+16
        bool sr8  = (fb0 >= 1.0f);      // unit r+8
        bool sr24 = (fb1 >= 1.0f);      // unit r+24
        u32 B0 = __ballot_sync(0xffffffffu, sr0);
        u32 B1 = __ballot_sync(0xffffffffu, sr8);
        u32 B2 = __ballot_sync(0xffffffffu, sr16);
        u32 B3 = __ballot_sync(0xffffffffu, sr24);
        v1a = pk(sr0 ? 0.0f : fa0, sr16 ? 0.0f : fa1);
        v1b = pk(sr8 ? 0.0f : fb0, sr24 ? 0.0f : fb1);

        // ---- 32-bit spike mask of elem 'me' via 3 PRMTs (bit k = unit k) ----
        u32 lo16 = __byte_perm(B0, B1, sel);
        u32 hi16 = __byte_perm(B2, B3, sel);
        u32 M    = __byte_perm(lo16, hi16, 0x5410);

        // ---- issue 4 byte-LUT LDGs now (L1D-resident, b2 folded in p4=0) ----
        u64 l0 = __ldg(reinterpret_cast<const u64*>(lj + (M & 255u) * 10));
        u64 l1 = __ldg(reinterpret_cast<const u64*>(lj + ((M >> 8)  & 255u) * 10 + 2560));
        u64 l2 = __ldg(reinterpret_cast<const u64*>(lj + ((M >> 16) & 255u) * 10 + 5120));
        u64 l3 = __ldg(reinterpret_cast<const u64*>(lj + (M >> 24) * 10 + 7680));

        // ---- overlap: h for t+1 (skip dead prefetch at t=27) ----
        u64 hn0 = 0ull, hn1 = 0ull;
        if (t < 27) COMPUTE_H(t + 1, hn0, hn1);

        // ---- layer 2: consume LUT (ascending p4: exact R13 order, b2 in l0) ----
        u64 h2 = l0;
        h2 = add2(h2, l1); h2 = add2(h2, l2); h2 = add2(h2, l3);

        // ---- IF layer 2 + integer rate accumulation ----
        v2p = add2(v2p, h2);
        float g0, g1; upk(g0, g1, v2p);
        bool t0 = (g0 >= 1.0f), t1 = (g1 >= 1.0f);
        ac0 += t0; ac1 += t1;
        v2p = pk(t0 ? 0.0f : g0, t1 ? 0.0f : g1);

        hc0 = hn0; hc1 = hn1;
    }

    // ---- output: lanes 0..19 write their (elem, j-pair) firing rates ----
    int ge = gbase + wid * EPW + me;
    if (lid < 20 && ge < B) {
        *reinterpret_cast<float2*>(out + (size_t)ge * 10 + 2 * jj) =
            make_float2((float)ac0 * (1.0f / 28.0f), (float)ac1 * (1.0f / 28.0f));
    }
}

extern "C" void kernel_launch(void* const* d_in, const int* in_sizes, int n_in,
                              void* d_out, int out_size) {
    const float* x  = (const float*)d_in[0];
    const float* W1 = (const float*)d_in[1];
    const float* b1 = (const float*)d_in[2];
    const float* W2 = (const float*)d_in[3];
    const float* b2 = (const float*)d_in[4];
    float* out = (float*)d_out;

    int B = in_sizes[0] / 784;
    int smem = SMEMW * (int)sizeof(float);   // ~58.1 KB -> 3 blocks/SM (12 warps)

    cudaFuncSetAttribute(snn_kernel, cudaFuncAttributeMaxDynamicSharedMemorySize, smem);

    build_lut<<<40, 256>>>(W2, b2);           // 10240 entries, one per thread

    int grid = (B + EPB - 1) / EPB;
    snn_kernel<<<grid, TPB, smem>>>(x, W1, b1, W2, b2, out, B);
}